// round 1
// baseline (speedup 1.0000x reference)
#include <cuda_runtime.h>

// Problem constants
constexpr int B_ = 8, E_ = 16, H_ = 256, W_ = 256;
constexpr int HW   = H_ * W_;        // 65536
constexpr int NPIX = B_ * HW;        // 524288
constexpr int TPB  = 256;
constexpr int NBLK = NPIX / TPB;     // 2048

// Scratch for deterministic two-stage reduction (no allocations allowed).
__device__ float g_partials[NBLK];

__global__ void __launch_bounds__(TPB)
crps_main_kernel(const float* __restrict__ fore, const float* __restrict__ obs) {
    const int g = blockIdx.x * TPB + threadIdx.x;   // pixel id in [0, NPIX)
    const int b = g >> 16;                          // g / HW  (HW = 65536)
    const int p = g & (HW - 1);                     // g % HW

    const float* fb = fore + ((size_t)b * E_) * HW + p;

    float f[E_];
#pragma unroll
    for (int e = 0; e < E_; e++) f[e] = __ldg(fb + (size_t)e * HW);

    const float o = __ldg(obs + g);

    // term1 numerator: sum_e |f_e - o|
    float s1 = 0.f;
#pragma unroll
    for (int e = 0; e < E_; e++) s1 += fabsf(f[e] - o);

    // Batcher odd-even mergesort network for 16 elements (63 comparators).
    // All loop bounds are compile-time -> fully unrolled, f[] stays in regs.
#pragma unroll
    for (int pp = 1; pp < E_; pp <<= 1) {
#pragma unroll
        for (int k = pp; k > 0; k >>= 1) {
#pragma unroll
            for (int j = k % pp; j + k < E_; j += 2 * k) {
#pragma unroll
                for (int i = 0; i < k; i++) {
                    if (i + j + k < E_) {
                        if ((i + j) / (pp * 2) == (i + j + k) / (pp * 2)) {
                            const int a = i + j, c = i + j + k;
                            const float lo = fminf(f[a], f[c]);
                            const float hi = fmaxf(f[a], f[c]);
                            f[a] = lo; f[c] = hi;
                        }
                    }
                }
            }
        }
    }

    // Pairwise-sum identity on sorted values:
    //   sum_{e<e'} |f_e - f_{e'}| = sum_i (2i - 15) * f_(i)   (ascending)
    float s2 = 0.f;
#pragma unroll
    for (int i = 0; i < E_; i++)
        s2 = fmaf((float)(2 * i - 15), f[i], s2);

    // per-pixel contribution: term1 - 0.5*term2
    //   term1 = s1/16 ; 0.5*term2 = 0.5 * (2*s2)/256 = s2/256
    const float val = s1 * (1.0f / 16.0f) - s2 * (1.0f / 256.0f);

    // Deterministic block reduction.
    __shared__ float sd[TPB];
    sd[threadIdx.x] = val;
    __syncthreads();
#pragma unroll
    for (int s = TPB / 2; s > 0; s >>= 1) {
        if (threadIdx.x < s) sd[threadIdx.x] += sd[threadIdx.x + s];
        __syncthreads();
    }
    if (threadIdx.x == 0) g_partials[blockIdx.x] = sd[0];
}

__global__ void __launch_bounds__(TPB)
crps_final_kernel(float* __restrict__ out) {
    __shared__ float sd[TPB];
    float s = 0.f;
#pragma unroll
    for (int i = threadIdx.x; i < NBLK; i += TPB) s += g_partials[i];
    sd[threadIdx.x] = s;
    __syncthreads();
#pragma unroll
    for (int st = TPB / 2; st > 0; st >>= 1) {
        if (threadIdx.x < st) sd[threadIdx.x] += sd[threadIdx.x + st];
        __syncthreads();
    }
    if (threadIdx.x == 0) out[0] = sd[0] * (1.0f / (float)NPIX);
}

extern "C" void kernel_launch(void* const* d_in, const int* in_sizes, int n_in,
                              void* d_out, int out_size) {
    const float* fore = (const float*)d_in[0];
    const float* obs  = (const float*)d_in[1];
    float* out = (float*)d_out;

    crps_main_kernel<<<NBLK, TPB>>>(fore, obs);
    crps_final_kernel<<<1, TPB>>>(out);
}